// round 4
// baseline (speedup 1.0000x reference)
#include <cuda_runtime.h>

#define N_NODE 4096
#define KNN 32
#define HIDDEN 128
#define RMS_EPS 1e-5f
#define TABLE_N 4096
#define NQ 8
#define CAND_CAP 768

__device__ float g_table[TABLE_N];
__device__ float4 g_pos4[N_NODE];

typedef unsigned long long u64;

static __device__ __forceinline__ u64 ullmin2(u64 a, u64 b) { return (b < a) ? b : a; }

// ---------------------------------------------------------------------------
// Kernel 0: pack pos into float4.
// ---------------------------------------------------------------------------
__global__ void prep_kernel(const float* __restrict__ pos) {
    int j = blockIdx.x * blockDim.x + threadIdx.x;
    if (j < N_NODE)
        g_pos4[j] = make_float4(pos[3 * j], pos[3 * j + 1], pos[3 * j + 2], 0.0f);
}

// ---------------------------------------------------------------------------
// Kernel 1: tabulate s(u), u = r/(1+r) on a uniform [0,1] grid of TABLE_N.
// Block = 128 thr = 4 warps; warp computes 4 samples. Lane owns 4 output
// channels in layer 2; h1 per warp in smem; W2 streamed from L2.
// ---------------------------------------------------------------------------
__global__ void __launch_bounds__(128, 8)
table_kernel(const float* __restrict__ t,
             const float* __restrict__ W1,
             const float* __restrict__ b1,
             const float* __restrict__ g1,
             const float* __restrict__ W2,
             const float* __restrict__ b2,
             const float* __restrict__ g2,
             const float* __restrict__ W3,
             const float* __restrict__ b3) {
    __shared__ float h1s[4][HIDDEN * 4];   // [warp][k*4 + q]
    __shared__ float sa[128], sc[128], sg1[128], sg2[128], sW3[128];
    __shared__ float sABC[3];
    __shared__ float sred[12];

    const int tid = threadIdx.x;
    const int w = tid >> 5, lane = tid & 31;

    // Per-channel params + closed-form L1 RMSNorm coefficients
    {
        const int k = tid;
        float t0 = t[0];
        float a = W1[2 * k];
        float c = fmaf(t0, W1[2 * k + 1], b1[k]);
        sa[k] = a; sc[k] = c;
        sg1[k] = g1[k]; sg2[k] = g2[k]; sW3[k] = W3[k];
        float pa = a * a, pb = a * c, pc = c * c;
        #pragma unroll
        for (int off = 16; off > 0; off >>= 1) {
            pa += __shfl_down_sync(0xffffffffu, pa, off);
            pb += __shfl_down_sync(0xffffffffu, pb, off);
            pc += __shfl_down_sync(0xffffffffu, pc, off);
        }
        if (lane == 0) { sred[w] = pa; sred[4 + w] = pb; sred[8 + w] = pc; }
    }
    __syncthreads();
    if (tid == 0) {
        const float inv = 1.0f / HIDDEN;
        sABC[0] = (sred[0] + sred[1] + sred[2] + sred[3]) * inv;
        sABC[1] = (sred[4] + sred[5] + sred[6] + sred[7]) * inv;
        sABC[2] = (sred[8] + sred[9] + sred[10] + sred[11]) * inv;
    }
    __syncthreads();

    const float A = sABC[0], Bc = sABC[1], C = sABC[2];
    const int s0 = blockIdx.x * 16 + w * 4;
    float* h1b = h1s[w];

    // Layer 1 for 4 samples
    #pragma unroll
    for (int q = 0; q < 4; q++) {
        float u = (float)(s0 + q) * (1.0f / (float)(TABLE_N - 1));
        float om = 1.0f - u;
        float r = (om > 1e-8f) ? (u / om) : 1e9f;
        float den = fmaf(fmaf(r, A, 2.0f * Bc), r, C) + RMS_EPS;
        float scl = rsqrtf(den);
        #pragma unroll
        for (int p = 0; p < 4; p++) {
            int k = lane + 32 * p;
            float x = fmaf(r, sa[k], sc[k]);
            float v = x * scl * sg1[k];
            float h = v * (1.0f / (1.0f + __expf(-v)));
            h1b[k * 4 + q] = h;
        }
    }
    __syncwarp();

    // Layer 2: lane owns m = lane + 32p, p<4; 4 samples each
    float acc[4][4];
    #pragma unroll
    for (int p = 0; p < 4; p++)
        #pragma unroll
        for (int q = 0; q < 4; q++) acc[p][q] = 0.0f;

    const float4* wr0 = (const float4*)(W2 + (lane)       * HIDDEN);
    const float4* wr1 = (const float4*)(W2 + (lane + 32)  * HIDDEN);
    const float4* wr2 = (const float4*)(W2 + (lane + 64)  * HIDDEN);
    const float4* wr3 = (const float4*)(W2 + (lane + 96)  * HIDDEN);
    #pragma unroll 2
    for (int kk = 0; kk < 32; kk++) {
        float4 w0 = __ldg(wr0 + kk), w1 = __ldg(wr1 + kk);
        float4 w2 = __ldg(wr2 + kk), w3 = __ldg(wr3 + kk);
        float w0a[4] = {w0.x, w0.y, w0.z, w0.w};
        float w1a[4] = {w1.x, w1.y, w1.z, w1.w};
        float w2a[4] = {w2.x, w2.y, w2.z, w2.w};
        float w3a[4] = {w3.x, w3.y, w3.z, w3.w};
        #pragma unroll
        for (int kq = 0; kq < 4; kq++) {
            float4 hv = *(const float4*)(h1b + (4 * kk + kq) * 4);
            float hva[4] = {hv.x, hv.y, hv.z, hv.w};
            #pragma unroll
            for (int q = 0; q < 4; q++) {
                acc[0][q] = fmaf(w0a[kq], hva[q], acc[0][q]);
                acc[1][q] = fmaf(w1a[kq], hva[q], acc[1][q]);
                acc[2][q] = fmaf(w2a[kq], hva[q], acc[2][q]);
                acc[3][q] = fmaf(w3a[kq], hva[q], acc[3][q]);
            }
        }
    }

    // + bias
    #pragma unroll
    for (int p = 0; p < 4; p++) {
        float bb = b2[lane + 32 * p];
        #pragma unroll
        for (int q = 0; q < 4; q++) acc[p][q] += bb;
    }

    // Layer-2 RMSNorm scale per sample
    float scl2[4];
    #pragma unroll
    for (int q = 0; q < 4; q++) {
        float ss = 0.0f;
        #pragma unroll
        for (int p = 0; p < 4; p++) ss = fmaf(acc[p][q], acc[p][q], ss);
        #pragma unroll
        for (int off = 16; off > 0; off >>= 1)
            ss += __shfl_xor_sync(0xffffffffu, ss, off);
        scl2[q] = rsqrtf(ss * (1.0f / HIDDEN) + RMS_EPS);
    }

    // h2 = silu(y*scale*g2) dot W3
    float dot[4] = {0.0f, 0.0f, 0.0f, 0.0f};
    #pragma unroll
    for (int p = 0; p < 4; p++) {
        int m = lane + 32 * p;
        float g = sg2[m], w3v = sW3[m];
        #pragma unroll
        for (int q = 0; q < 4; q++) {
            float v = acc[p][q] * scl2[q] * g;
            float h = v * (1.0f / (1.0f + __expf(-v)));
            dot[q] = fmaf(w3v, h, dot[q]);
        }
    }
    #pragma unroll
    for (int q = 0; q < 4; q++) {
        #pragma unroll
        for (int off = 16; off > 0; off >>= 1)
            dot[q] += __shfl_xor_sync(0xffffffffu, dot[q], off);
    }
    if (lane == 0) {
        float bb3 = b3[0];
        #pragma unroll
        for (int q = 0; q < 4; q++) g_table[s0 + q] = dot[q] + bb3;
    }
}

// ---------------------------------------------------------------------------
// Kernel 2: fused kNN + eval. Block = 256 thr = 8 warps = 8 queries.
// Phase 1: per-warp 256-point sample -> threshold tau (16th smallest).
// Phase 2: filter all 4096 (cooperative pos tiles, ballot-compaction, no
//          atomics) -> candidate list; block-level deterministic retry
//          guarantees 32 <= cnt <= CAND_CAP (exactness).
// Phase 3: per-warp 256-bucket radix refine on candidates -> rank-32 bucket.
// Phase 4: below-bucket edges accumulate s(r)*d directly; boundary bucket
//          extracted by (bits,index)-min rounds (exact jax top_k tie-break).
// ---------------------------------------------------------------------------
__global__ void __launch_bounds__(256, 3)
knn_eval_kernel(float* __restrict__ out) {
    extern __shared__ __align__(16) char smraw[];
    float4*   tile  = (float4*)smraw;                       // 512 * 16 = 8192
    u64*      cand  = (u64*)(smraw + 8192);                 // 8*768*8 = 49152
    unsigned* hist  = (unsigned*)(smraw + 8192 + 49152);    // 8*256*4 = 8192
    int*      s_need = (int*)(smraw + 8192 + 49152 + 8192);

    const int tid = threadIdx.x;
    const int w = tid >> 5, lane = tid & 31;
    const int i = blockIdx.x * NQ + w;
    const float INF = __int_as_float(0x7f800000);

    const float4 pi = g_pos4[i];
    u64* mycand = cand + w * CAND_CAP;
    unsigned* myhist = hist + w * 256;

    // ---- Phase 1: sample 256 points, tau = 16th smallest ----
    float ds[8];
    #pragma unroll
    for (int s = 0; s < 8; s++) {
        int j = s * 512 + lane * 16;
        float4 q = g_pos4[j];
        float dx = pi.x - q.x, dy = pi.y - q.y, dz = pi.z - q.z;
        float d = fmaf(dx, dx, fmaf(dy, dy, dz * dz));
        ds[s] = (j == i) ? INF : d;
    }
    float tau = 0.0f;
    for (int rr = 0; rr < 16; rr++) {
        float m = ds[0];
        #pragma unroll
        for (int s = 1; s < 8; s++) m = fminf(m, ds[s]);
        #pragma unroll
        for (int off = 16; off > 0; off >>= 1)
            m = fminf(m, __shfl_xor_sync(0xffffffffu, m, off));
        bool removed = false;
        #pragma unroll
        for (int s = 0; s < 8; s++) {
            if (!removed && ds[s] == m) { ds[s] = INF; removed = true; }
        }
        tau = m;
    }

    // ---- Phase 2: filter with block-level retry ----
    int cnt = 0;
    while (true) {
        cnt = 0;
        for (int tb = 0; tb < 8; tb++) {
            __syncthreads();
            tile[tid]       = g_pos4[tb * 512 + tid];
            tile[256 + tid] = g_pos4[tb * 512 + 256 + tid];
            __syncthreads();
            #pragma unroll 4
            for (int it = 0; it < 16; it++) {
                int jl = it * 32 + lane;
                int j = tb * 512 + jl;
                float4 q = tile[jl];
                float dx = pi.x - q.x, dy = pi.y - q.y, dz = pi.z - q.z;
                float d = fmaf(dx, dx, fmaf(dy, dy, dz * dz));
                bool p = (d <= tau) && (j != i);
                unsigned mask = __ballot_sync(0xffffffffu, p);
                if (p) {
                    int pos = cnt + __popc(mask & ((1u << lane) - 1u));
                    if (pos < CAND_CAP)
                        mycand[pos] = ((u64)__float_as_uint(d) << 32) | (unsigned)j;
                }
                cnt += __popc(mask);
            }
        }
        __syncthreads();
        if (tid == 0) *s_need = 0;
        __syncthreads();
        bool ok = (cnt >= KNN && cnt <= CAND_CAP);
        if (!ok) {
            if (lane == 0) *s_need = 1;
            tau = (cnt < KNN) ? fmaxf(tau * 4.0f, 1e-12f) : (tau * 0.5f);
        }
        __syncthreads();
        if (*s_need == 0) break;
    }

    // ---- Phase 3: per-warp radix refine ----
    for (int b = lane; b < 256; b += 32) myhist[b] = 0;
    __syncwarp();
    const unsigned taub = __float_as_uint(tau);
    const int bl = 32 - __clz(taub | 1u);
    const int sh = (bl > 8) ? (bl - 8) : 0;
    for (int c = lane; c < cnt; c += 32) {
        unsigned bits = (unsigned)(mycand[c] >> 32);
        atomicAdd(&myhist[bits >> sh], 1u);
    }
    __syncwarp();

    unsigned hv[8];
    unsigned lsum = 0;
    #pragma unroll
    for (int q = 0; q < 8; q++) { hv[q] = myhist[lane * 8 + q]; lsum += hv[q]; }
    unsigned run = lsum;
    #pragma unroll
    for (int off = 1; off < 32; off <<= 1) {
        unsigned v = __shfl_up_sync(0xffffffffu, run, off);
        if (lane >= off) run += v;
    }
    run -= lsum;  // exclusive prefix
    u64 pk = 0;
    {
        unsigned r2 = run;
        #pragma unroll
        for (int q = 0; q < 8; q++) {
            if (r2 < KNN && r2 + hv[q] >= KNN)
                pk = ((u64)(unsigned)(lane * 8 + q) << 32) | r2;
            r2 += hv[q];
        }
    }
    #pragma unroll
    for (int off = 16; off > 0; off >>= 1) {
        u64 o = __shfl_xor_sync(0xffffffffu, pk, off);
        if (o > pk) pk = o;
    }
    const int B2 = (int)(pk >> 32);
    const int base = (int)(pk & 0xffffffffu);

    // ---- Phase 4: accumulate ----
    const float tscale = (float)(TABLE_N - 1);
    float sx = 0.0f, sy = 0.0f, sz = 0.0f;

    // helper lambda (inlined manually): accumulate edge given key
    #define ACCUM_EDGE(key) do {                                            \
        unsigned _bits = (unsigned)((key) >> 32);                           \
        int _j = (int)((key) & 0xffffffffu);                                \
        float4 _q = g_pos4[_j];                                             \
        float _dx = pi.x - _q.x, _dy = pi.y - _q.y, _dz = pi.z - _q.z;      \
        float _r = __uint_as_float(_bits);                                  \
        float _u = _r / (1.0f + _r);                                        \
        float _x = _u * tscale;                                             \
        int _i0 = (int)_x; if (_i0 > TABLE_N - 2) _i0 = TABLE_N - 2;        \
        float _f = _x - (float)_i0;                                         \
        float _s0 = g_table[_i0], _s1 = g_table[_i0 + 1];                   \
        float _sv = fmaf(_f, _s1 - _s0, _s0);                               \
        sx = fmaf(_dx, _sv, sx);                                            \
        sy = fmaf(_dy, _sv, sy);                                            \
        sz = fmaf(_dz, _sv, sz);                                            \
    } while (0)

    // below-boundary-bucket edges
    for (int c = lane; c < cnt; c += 32) {
        u64 key = mycand[c];
        unsigned bits = (unsigned)(key >> 32);
        if ((int)(bits >> sh) < B2) ACCUM_EDGE(key);
    }

    // boundary bucket: extract (KNN - base) smallest by (bits, idx)
    int need = KNN - base;
    for (int s = 0; s < need; s++) {
        u64 best = ~0ull;
        for (int c = lane; c < cnt; c += 32) {
            u64 k2 = mycand[c];
            if (k2 != ~0ull && (int)(((unsigned)(k2 >> 32)) >> sh) == B2)
                best = ullmin2(best, k2);
        }
        #pragma unroll
        for (int off = 16; off > 0; off >>= 1)
            best = ullmin2(best, __shfl_xor_sync(0xffffffffu, best, off));
        if (lane == 0 && best != ~0ull) ACCUM_EDGE(best);
        for (int c = lane; c < cnt; c += 32)
            if (mycand[c] == best) mycand[c] = ~0ull;
    }

    // warp reduce + write
    #pragma unroll
    for (int off = 16; off > 0; off >>= 1) {
        sx += __shfl_down_sync(0xffffffffu, sx, off);
        sy += __shfl_down_sync(0xffffffffu, sy, off);
        sz += __shfl_down_sync(0xffffffffu, sz, off);
    }
    if (lane == 0) {
        const float invK = 1.0f / (float)KNN;
        out[3 * i]     = pi.x + sx * invK;
        out[3 * i + 1] = pi.y + sy * invK;
        out[3 * i + 2] = pi.z + sz * invK;
    }
    #undef ACCUM_EDGE
}

// ---------------------------------------------------------------------------
// Launch
// ---------------------------------------------------------------------------
extern "C" void kernel_launch(void* const* d_in, const int* in_sizes, int n_in,
                              void* d_out, int out_size) {
    const float* pos = (const float*)d_in[0];
    const float* t   = (const float*)d_in[1];
    const float* W1  = (const float*)d_in[2];
    const float* b1  = (const float*)d_in[3];
    const float* g1  = (const float*)d_in[4];
    const float* W2  = (const float*)d_in[5];
    const float* b2  = (const float*)d_in[6];
    const float* g2  = (const float*)d_in[7];
    const float* W3  = (const float*)d_in[8];
    const float* b3  = (const float*)d_in[9];
    float* out = (float*)d_out;

    const int knn_smem = 8192 + 49152 + 8192 + 16;
    cudaFuncSetAttribute(knn_eval_kernel, cudaFuncAttributeMaxDynamicSharedMemorySize, knn_smem);

    prep_kernel<<<(N_NODE + 255) / 256, 256>>>(pos);
    table_kernel<<<TABLE_N / 16, 128>>>(t, W1, b1, g1, W2, b2, g2, W3, b3);
    knn_eval_kernel<<<N_NODE / NQ, 256, knn_smem>>>(out);
}

// round 5
// speedup vs baseline: 1.3981x; 1.3981x over previous
#include <cuda_runtime.h>

#define N_NODE 4096
#define KNN 32
#define HIDDEN 128
#define RMS_EPS 1e-5f
#define TABLE_N 4096
#define NQ 8
#define NBUCK 1024
#define CAP 128

__device__ float g_table[TABLE_N];
__device__ float4 g_pos4[N_NODE];

typedef unsigned long long u64;

static __device__ __forceinline__ u64 ullmin2(u64 a, u64 b) { return (b < a) ? b : a; }

// ---------------------------------------------------------------------------
// Kernel 1: table of s(u), u = r/(1+r), uniform grid; prep fused in the same
// launch (blocks >= TABLE_N/16 pack pos into float4).
// Table blocks: 128 thr = 4 warps; warp computes 4 samples; lane owns 4
// output channels in layer 2; h1 per warp in smem; W2 streamed from L2.
// ---------------------------------------------------------------------------
__global__ void __launch_bounds__(128, 8)
table_prep_kernel(const float* __restrict__ pos,
                  const float* __restrict__ t,
                  const float* __restrict__ W1,
                  const float* __restrict__ b1,
                  const float* __restrict__ g1,
                  const float* __restrict__ W2,
                  const float* __restrict__ b2,
                  const float* __restrict__ g2,
                  const float* __restrict__ W3,
                  const float* __restrict__ b3) {
    const int tid = threadIdx.x;

    if (blockIdx.x >= TABLE_N / 16) {
        // ---- prep branch: pack pos into float4 ----
        int j = (blockIdx.x - TABLE_N / 16) * 128 + tid;
        if (j < N_NODE)
            g_pos4[j] = make_float4(pos[3 * j], pos[3 * j + 1], pos[3 * j + 2], 0.0f);
        return;
    }

    __shared__ float h1s[4][HIDDEN * 4];   // [warp][k*4 + q]
    __shared__ float sa[128], sc[128], sg1[128], sg2[128], sW3[128];
    __shared__ float sABC[3];
    __shared__ float sred[12];

    const int w = tid >> 5, lane = tid & 31;

    // Per-channel params + closed-form L1 RMSNorm coefficients
    {
        const int k = tid;
        float t0 = t[0];
        float a = W1[2 * k];
        float c = fmaf(t0, W1[2 * k + 1], b1[k]);
        sa[k] = a; sc[k] = c;
        sg1[k] = g1[k]; sg2[k] = g2[k]; sW3[k] = W3[k];
        float pa = a * a, pb = a * c, pc = c * c;
        #pragma unroll
        for (int off = 16; off > 0; off >>= 1) {
            pa += __shfl_down_sync(0xffffffffu, pa, off);
            pb += __shfl_down_sync(0xffffffffu, pb, off);
            pc += __shfl_down_sync(0xffffffffu, pc, off);
        }
        if (lane == 0) { sred[w] = pa; sred[4 + w] = pb; sred[8 + w] = pc; }
    }
    __syncthreads();
    if (tid == 0) {
        const float inv = 1.0f / HIDDEN;
        sABC[0] = (sred[0] + sred[1] + sred[2] + sred[3]) * inv;
        sABC[1] = (sred[4] + sred[5] + sred[6] + sred[7]) * inv;
        sABC[2] = (sred[8] + sred[9] + sred[10] + sred[11]) * inv;
    }
    __syncthreads();

    const float A = sABC[0], Bc = sABC[1], C = sABC[2];
    const int s0 = blockIdx.x * 16 + w * 4;
    float* h1b = h1s[w];

    // Layer 1 for 4 samples
    #pragma unroll
    for (int q = 0; q < 4; q++) {
        float u = (float)(s0 + q) * (1.0f / (float)(TABLE_N - 1));
        float om = 1.0f - u;
        float r = (om > 1e-8f) ? (u / om) : 1e9f;
        float den = fmaf(fmaf(r, A, 2.0f * Bc), r, C) + RMS_EPS;
        float scl = rsqrtf(den);
        #pragma unroll
        for (int p = 0; p < 4; p++) {
            int k = lane + 32 * p;
            float x = fmaf(r, sa[k], sc[k]);
            float v = x * scl * sg1[k];
            float h = v * (1.0f / (1.0f + __expf(-v)));
            h1b[k * 4 + q] = h;
        }
    }
    __syncwarp();

    // Layer 2: lane owns m = lane + 32p, p<4; 4 samples each
    float acc[4][4];
    #pragma unroll
    for (int p = 0; p < 4; p++)
        #pragma unroll
        for (int q = 0; q < 4; q++) acc[p][q] = 0.0f;

    const float4* wr0 = (const float4*)(W2 + (lane)      * HIDDEN);
    const float4* wr1 = (const float4*)(W2 + (lane + 32) * HIDDEN);
    const float4* wr2 = (const float4*)(W2 + (lane + 64) * HIDDEN);
    const float4* wr3 = (const float4*)(W2 + (lane + 96) * HIDDEN);
    #pragma unroll 2
    for (int kk = 0; kk < 32; kk++) {
        float4 w0 = __ldg(wr0 + kk), w1 = __ldg(wr1 + kk);
        float4 w2 = __ldg(wr2 + kk), w3 = __ldg(wr3 + kk);
        float w0a[4] = {w0.x, w0.y, w0.z, w0.w};
        float w1a[4] = {w1.x, w1.y, w1.z, w1.w};
        float w2a[4] = {w2.x, w2.y, w2.z, w2.w};
        float w3a[4] = {w3.x, w3.y, w3.z, w3.w};
        #pragma unroll
        for (int kq = 0; kq < 4; kq++) {
            float4 hv = *(const float4*)(h1b + (4 * kk + kq) * 4);
            float hva[4] = {hv.x, hv.y, hv.z, hv.w};
            #pragma unroll
            for (int q = 0; q < 4; q++) {
                acc[0][q] = fmaf(w0a[kq], hva[q], acc[0][q]);
                acc[1][q] = fmaf(w1a[kq], hva[q], acc[1][q]);
                acc[2][q] = fmaf(w2a[kq], hva[q], acc[2][q]);
                acc[3][q] = fmaf(w3a[kq], hva[q], acc[3][q]);
            }
        }
    }

    // + bias
    #pragma unroll
    for (int p = 0; p < 4; p++) {
        float bb = b2[lane + 32 * p];
        #pragma unroll
        for (int q = 0; q < 4; q++) acc[p][q] += bb;
    }

    // Layer-2 RMSNorm scale per sample
    float scl2[4];
    #pragma unroll
    for (int q = 0; q < 4; q++) {
        float ss = 0.0f;
        #pragma unroll
        for (int p = 0; p < 4; p++) ss = fmaf(acc[p][q], acc[p][q], ss);
        #pragma unroll
        for (int off = 16; off > 0; off >>= 1)
            ss += __shfl_xor_sync(0xffffffffu, ss, off);
        scl2[q] = rsqrtf(ss * (1.0f / HIDDEN) + RMS_EPS);
    }

    // h2 = silu(y*scale*g2) dot W3
    float dot[4] = {0.0f, 0.0f, 0.0f, 0.0f};
    #pragma unroll
    for (int p = 0; p < 4; p++) {
        int m = lane + 32 * p;
        float g = sg2[m], w3v = sW3[m];
        #pragma unroll
        for (int q = 0; q < 4; q++) {
            float v = acc[p][q] * scl2[q] * g;
            float h = v * (1.0f / (1.0f + __expf(-v)));
            dot[q] = fmaf(w3v, h, dot[q]);
        }
    }
    #pragma unroll
    for (int q = 0; q < 4; q++) {
        #pragma unroll
        for (int off = 16; off > 0; off >>= 1)
            dot[q] += __shfl_xor_sync(0xffffffffu, dot[q], off);
    }
    if (lane == 0) {
        float bb3 = b3[0];
        #pragma unroll
        for (int q = 0; q < 4; q++) g_table[s0 + q] = dot[q] + bb3;
    }
}

// ---------------------------------------------------------------------------
// Kernel 2: fused kNN + eval. Block = 256 thr = 8 warps = 8 queries.
// Pass 1: exact per-warp 1024-bucket histogram over all 4096 distances
//         (cooperative 512-point position tiles in smem).
// Warp-scan locates the rank-32 bucket B and base count exactly (no retry).
// Pass 2: recompute distances (bitwise identical); bucket<B edges accumulate
//         s(r)*d directly; bucket==B go to a small candidate list.
// Boundary bucket: exact (bits,index)-min extraction (jax top_k tie-break).
// Deterministic direct-rescan fallback if boundary bucket > CAP (prob ~0).
// ---------------------------------------------------------------------------
__global__ void __launch_bounds__(256, 4)
knn_eval_kernel(float* __restrict__ out) {
    __shared__ float4 tile[512];                 // 8 KB
    __shared__ unsigned hist[NQ][NBUCK];         // 32 KB
    __shared__ u64 cand[NQ][CAP];                // 8 KB
    __shared__ int ccnt[NQ];

    const int tid = threadIdx.x;
    const int w = tid >> 5, lane = tid & 31;
    const int i = blockIdx.x * NQ + w;
    const float4 pi = g_pos4[i];
    unsigned* myhist = hist[w];
    u64* mycand = cand[w];

    for (int b = lane; b < NBUCK; b += 32) myhist[b] = 0;
    if (lane == 0) ccnt[w] = 0;

    // ---- Pass 1: histogram ----
    for (int tb = 0; tb < 8; tb++) {
        __syncthreads();
        tile[tid]       = g_pos4[tb * 512 + tid];
        tile[tid + 256] = g_pos4[tb * 512 + 256 + tid];
        __syncthreads();
        #pragma unroll 4
        for (int it = 0; it < 16; it++) {
            int jl = it * 32 + lane;
            float4 q = tile[jl];
            float dx = pi.x - q.x, dy = pi.y - q.y, dz = pi.z - q.z;
            float d = fmaf(dx, dx, fmaf(dy, dy, dz * dz));
            int j = tb * 512 + jl;
            unsigned bits = (j == i) ? 0x7f800000u : __float_as_uint(d);
            atomicAdd(&myhist[bits >> 21], 1u);
        }
    }
    __syncwarp();

    // ---- Scan 1024 buckets; lane owns [lane*32, lane*32+32) ----
    const int b0 = lane * 32;
    unsigned lsum = 0;
    #pragma unroll 8
    for (int q = 0; q < 32; q++) lsum += myhist[b0 + q];
    unsigned run = lsum;
    #pragma unroll
    for (int off = 1; off < 32; off <<= 1) {
        unsigned v = __shfl_up_sync(0xffffffffu, run, off);
        if (lane >= off) run += v;
    }
    run -= lsum;  // exclusive prefix
    u64 pk = 0;
    {
        unsigned r2 = run;
        #pragma unroll 8
        for (int q = 0; q < 32; q++) {
            unsigned h = myhist[b0 + q];
            if (r2 < KNN && r2 + h >= KNN)
                pk = ((u64)(unsigned)(b0 + q) << 32) | r2;
            r2 += h;
        }
    }
    #pragma unroll
    for (int off = 16; off > 0; off >>= 1) {
        u64 o = __shfl_xor_sync(0xffffffffu, pk, off);
        if (o > pk) pk = o;
    }
    const int B2 = (int)(pk >> 32);
    const int base = (int)(pk & 0xffffffffu);
    const unsigned hb2 = myhist[B2];
    __syncwarp();

    // ---- Pass 2: accumulate below-bucket edges, collect boundary bucket ----
    const float tscale = (float)(TABLE_N - 1);
    float sx = 0.0f, sy = 0.0f, sz = 0.0f;

    #define ACCUM_EDGE(_bits, _dx, _dy, _dz) do {                          \
        float _r = __uint_as_float(_bits);                                 \
        float _u = _r / (1.0f + _r);                                       \
        float _x = _u * tscale;                                            \
        int _i0 = (int)_x; if (_i0 > TABLE_N - 2) _i0 = TABLE_N - 2;       \
        float _f = _x - (float)_i0;                                        \
        float _s0 = g_table[_i0], _s1 = g_table[_i0 + 1];                  \
        float _sv = fmaf(_f, _s1 - _s0, _s0);                              \
        sx = fmaf(_dx, _sv, sx);                                           \
        sy = fmaf(_dy, _sv, sy);                                           \
        sz = fmaf(_dz, _sv, sz);                                           \
    } while (0)

    const bool small_bucket = (hb2 <= CAP);
    for (int tb = 0; tb < 8; tb++) {
        __syncthreads();
        tile[tid]       = g_pos4[tb * 512 + tid];
        tile[tid + 256] = g_pos4[tb * 512 + 256 + tid];
        __syncthreads();
        #pragma unroll 4
        for (int it = 0; it < 16; it++) {
            int jl = it * 32 + lane;
            float4 q = tile[jl];
            float dx = pi.x - q.x, dy = pi.y - q.y, dz = pi.z - q.z;
            float d = fmaf(dx, dx, fmaf(dy, dy, dz * dz));
            int j = tb * 512 + jl;
            unsigned bits = (j == i) ? 0x7f800000u : __float_as_uint(d);
            int bk = (int)(bits >> 21);
            if (bk < B2) {
                ACCUM_EDGE(bits, dx, dy, dz);
            } else if (bk == B2 && small_bucket) {
                int p = atomicAdd(&ccnt[w], 1);
                mycand[p] = ((u64)bits << 32) | (unsigned)j;
            }
        }
    }
    __syncwarp();

    // ---- Boundary bucket: extract (KNN - base) smallest by (bits, idx) ----
    const int need = KNN - base;
    if (small_bucket) {
        const int cn = ccnt[w];
        for (int s = 0; s < need; s++) {
            u64 best = ~0ull;
            for (int c = lane; c < cn; c += 32) best = ullmin2(best, mycand[c]);
            #pragma unroll
            for (int off = 16; off > 0; off >>= 1)
                best = ullmin2(best, __shfl_xor_sync(0xffffffffu, best, off));
            if (lane == 0) {
                unsigned bb = (unsigned)(best >> 32);
                int j = (int)(best & 0xffffffffu);
                float4 q = g_pos4[j];
                float dx = pi.x - q.x, dy = pi.y - q.y, dz = pi.z - q.z;
                ACCUM_EDGE(bb, dx, dy, dz);
            }
            for (int c = lane; c < cn; c += 32)
                if (mycand[c] == best) mycand[c] = ~0ull;
        }
    } else {
        // Fallback (boundary bucket overflow; probability ~0): direct rescan
        u64 last = 0;
        for (int s = 0; s < need; s++) {
            u64 best = ~0ull;
            for (int j0 = lane; j0 < N_NODE; j0 += 32) {
                float4 q = g_pos4[j0];
                float dx = pi.x - q.x, dy = pi.y - q.y, dz = pi.z - q.z;
                float d = fmaf(dx, dx, fmaf(dy, dy, dz * dz));
                unsigned bits = (j0 == i) ? 0x7f800000u : __float_as_uint(d);
                if ((int)(bits >> 21) == B2) {
                    u64 key = ((u64)bits << 32) | (unsigned)j0;
                    if (key > last) best = ullmin2(best, key);
                }
            }
            #pragma unroll
            for (int off = 16; off > 0; off >>= 1)
                best = ullmin2(best, __shfl_xor_sync(0xffffffffu, best, off));
            if (lane == 0 && best != ~0ull) {
                unsigned bb = (unsigned)(best >> 32);
                int j = (int)(best & 0xffffffffu);
                float4 q = g_pos4[j];
                float dx = pi.x - q.x, dy = pi.y - q.y, dz = pi.z - q.z;
                ACCUM_EDGE(bb, dx, dy, dz);
            }
            last = best;
        }
    }
    #undef ACCUM_EDGE

    // ---- Warp reduce + write ----
    #pragma unroll
    for (int off = 16; off > 0; off >>= 1) {
        sx += __shfl_down_sync(0xffffffffu, sx, off);
        sy += __shfl_down_sync(0xffffffffu, sy, off);
        sz += __shfl_down_sync(0xffffffffu, sz, off);
    }
    if (lane == 0) {
        const float invK = 1.0f / (float)KNN;
        out[3 * i]     = pi.x + sx * invK;
        out[3 * i + 1] = pi.y + sy * invK;
        out[3 * i + 2] = pi.z + sz * invK;
    }
}

// ---------------------------------------------------------------------------
// Launch
// ---------------------------------------------------------------------------
extern "C" void kernel_launch(void* const* d_in, const int* in_sizes, int n_in,
                              void* d_out, int out_size) {
    const float* pos = (const float*)d_in[0];
    const float* t   = (const float*)d_in[1];
    const float* W1  = (const float*)d_in[2];
    const float* b1  = (const float*)d_in[3];
    const float* g1  = (const float*)d_in[4];
    const float* W2  = (const float*)d_in[5];
    const float* b2  = (const float*)d_in[6];
    const float* g2  = (const float*)d_in[7];
    const float* W3  = (const float*)d_in[8];
    const float* b3  = (const float*)d_in[9];
    float* out = (float*)d_out;

    const int table_blocks = TABLE_N / 16;            // 256
    const int prep_blocks  = (N_NODE + 127) / 128;    // 32
    table_prep_kernel<<<table_blocks + prep_blocks, 128>>>(
        pos, t, W1, b1, g1, W2, b2, g2, W3, b3);
    knn_eval_kernel<<<N_NODE / NQ, 256>>>(out);
}